// round 2
// baseline (speedup 1.0000x reference)
#include <cuda_runtime.h>
#include <cstdint>

#define B   32
#define T   512
#define MIN 4
#define H   512
#define H2  1024
#define H3  1536
#define BT  (B*T)

#define NB  64   // blocks per direction in recurrent kernel
#define JS  8    // hidden dims per block (NB*JS == H)
#define HP  516  // padded h row stride (words): lane starting banks disjoint
#define WP  516  // padded W row stride (words)

// ---------------- device scratch (static, no allocation) ----------------
__device__ float    g_embx[BT * H];
__device__ float    g_gx0[(size_t)BT * H3];
__device__ float    g_gx1[(size_t)BT * H3];
__device__ float    g_outcat[(size_t)BT * H2];
__device__ float    g_hcat[B * H2];
__device__ float    g_hbuf[2][2][B * H];
__device__ unsigned g_bar[2];

// ---------------- init ----------------
__global__ void init_kernel() {
    int tid = blockIdx.x * blockDim.x + threadIdx.x;
    if (tid < 2) g_bar[tid] = 0;
    for (int i = tid; i < B * H; i += gridDim.x * blockDim.x) {
        g_hbuf[0][0][i] = 0.f;
        g_hbuf[1][0][i] = 0.f;
    }
}

// ---------------- embedding gather + sum ----------------
__global__ void embed_kernel(const int* __restrict__ seqs,
                             const float* __restrict__ emb) {
    int bt = blockIdx.x;
    int i4 = threadIdx.x * 4;
    const int* s = seqs + bt * MIN;
    float4 acc = make_float4(0.f, 0.f, 0.f, 0.f);
#pragma unroll
    for (int m = 0; m < MIN; m++) {
        size_t row = (size_t)s[m] * H;
        float4 v = *reinterpret_cast<const float4*>(emb + row + i4);
        acc.x += v.x; acc.y += v.y; acc.z += v.z; acc.w += v.w;
    }
    *reinterpret_cast<float4*>(g_embx + (size_t)bt * H + i4) = acc;
}

// ---------------- fp32 GEMM: C[M,N] = A[M,K] @ W[K,N] + bias ----------------
// tile 128x128, BK=16, 256 threads, 8x8 micro-tile. K%16==0, N%128==0.
__global__ void gemm_bias_kernel(const float* __restrict__ A,
                                 const float* __restrict__ W,
                                 const float* __restrict__ bias,
                                 float* __restrict__ C,
                                 int Mr, int N, int K) {
    __shared__ float a_s[16][136];   // [k][m], padded
    __shared__ float b_s[16][128];   // [k][n]
    const int tid = threadIdx.x;
    const int m0  = blockIdx.y * 128;
    const int n0  = blockIdx.x * 128;
    const int tr  = tid >> 4;        // 0..15 -> 8 m-rows each
    const int tc  = tid & 15;        // 0..15 -> 8 n-cols each

    float acc[8][8];
#pragma unroll
    for (int i = 0; i < 8; i++)
#pragma unroll
        for (int j = 0; j < 8; j++) acc[i][j] = 0.f;

    for (int kt = 0; kt < K; kt += 16) {
        // A tile: 128x16 (2 float4 / thread), stored transposed [k][m]
#pragma unroll
        for (int l = 0; l < 2; l++) {
            int lin = tid + l * 256;
            int m  = lin >> 2;
            int kk = (lin & 3) * 4;
            float4 v = make_float4(0.f, 0.f, 0.f, 0.f);
            if (m0 + m < Mr)
                v = *reinterpret_cast<const float4*>(A + (size_t)(m0 + m) * K + kt + kk);
            a_s[kk + 0][m] = v.x; a_s[kk + 1][m] = v.y;
            a_s[kk + 2][m] = v.z; a_s[kk + 3][m] = v.w;
        }
        // B tile: 16x128 (2 float4 / thread)
#pragma unroll
        for (int l = 0; l < 2; l++) {
            int lin = tid + l * 256;
            int kk = lin >> 5;
            int n  = (lin & 31) * 4;
            float4 v = *reinterpret_cast<const float4*>(W + (size_t)(kt + kk) * N + n0 + n);
            *reinterpret_cast<float4*>(&b_s[kk][n]) = v;
        }
        __syncthreads();
#pragma unroll
        for (int kk = 0; kk < 16; kk++) {
            float a[8], bb[8];
            *reinterpret_cast<float4*>(&a[0])  = *reinterpret_cast<const float4*>(&a_s[kk][tr * 8]);
            *reinterpret_cast<float4*>(&a[4])  = *reinterpret_cast<const float4*>(&a_s[kk][tr * 8 + 4]);
            *reinterpret_cast<float4*>(&bb[0]) = *reinterpret_cast<const float4*>(&b_s[kk][tc * 8]);
            *reinterpret_cast<float4*>(&bb[4]) = *reinterpret_cast<const float4*>(&b_s[kk][tc * 8 + 4]);
#pragma unroll
            for (int i = 0; i < 8; i++)
#pragma unroll
                for (int j = 0; j < 8; j++)
                    acc[i][j] = fmaf(a[i], bb[j], acc[i][j]);
        }
        __syncthreads();
    }
    float bv[8];
    *reinterpret_cast<float4*>(&bv[0]) = *reinterpret_cast<const float4*>(bias + n0 + tc * 8);
    *reinterpret_cast<float4*>(&bv[4]) = *reinterpret_cast<const float4*>(bias + n0 + tc * 8 + 4);
#pragma unroll
    for (int i = 0; i < 8; i++) {
        int m = m0 + tr * 8 + i;
        if (m < Mr) {
            float4 o0, o1;
            o0.x = acc[i][0] + bv[0]; o0.y = acc[i][1] + bv[1];
            o0.z = acc[i][2] + bv[2]; o0.w = acc[i][3] + bv[3];
            o1.x = acc[i][4] + bv[4]; o1.y = acc[i][5] + bv[5];
            o1.z = acc[i][6] + bv[6]; o1.w = acc[i][7] + bv[7];
            *reinterpret_cast<float4*>(C + (size_t)m * N + n0 + tc * 8)     = o0;
            *reinterpret_cast<float4*>(C + (size_t)m * N + n0 + tc * 8 + 4) = o1;
        }
    }
}

// ---------------- persistent bidirectional GRU recurrence ----------------
// grid = 2*NB blocks, 256 threads. Block owns JS hidden dims.
// Lane mapping: b = tid>>3 (0..31), cg = tid&7 (0..7) -> within a warp:
//   h loads hit 4 distinct b rows (stride 516 words, disjoint banks, 8-way bcast)
//   w loads hit 8 distinct cols (stride 516 words, disjoint banks, 4-way bcast)
// => conflict-free shared traffic.
__global__ void gru_kernel(const float* __restrict__ Wh_f,
                           const float* __restrict__ brec_f,
                           const float* __restrict__ Wh_b,
                           const float* __restrict__ brec_b) {
    extern __shared__ float sm[];
    float* h_s = sm;                   // [B][HP]
    float* W_s = sm + B * HP;          // [3*JS][WP]: rows 0..7 z, 8..15 r, 16..23 n

    const int dir = blockIdx.x / NB;
    const int jb  = blockIdx.x % NB;
    const int j0  = jb * JS;
    const int tid = threadIdx.x;
    const int b   = tid >> 3;          // 0..31
    const int cg  = tid & 7;           // 0..7
    const int j   = j0 + cg;

    const float* Wh   = dir ? Wh_b   : Wh_f;
    const float* brec = dir ? brec_b : brec_f;
    const float* gx   = dir ? g_gx1  : g_gx0;

    // one-time: Wh slice -> SMEM (row c = gate-major local column)
    for (int idx = tid; idx < 3 * JS * H; idx += blockDim.x) {
        int c  = idx >> 9;             // 0..23
        int k  = idx & (H - 1);
        int part = c / JS;             // 0=z 1=r 2=n
        int jj   = c % JS;
        W_s[c * WP + k] = Wh[(size_t)k * H3 + part * H + j0 + jj];
    }
    const float brz = brec[j];
    const float brr = brec[H + j];
    const float brn = brec[2 * H + j];
    __syncthreads();

    float* hbuf0 = g_hbuf[dir][0];
    float* hbuf1 = g_hbuf[dir][1];
    volatile unsigned* bar = &g_bar[dir];

    for (int s = 0; s < T; s++) {
        const int t = dir ? (T - 1 - s) : s;
        const float* hin  = (s & 1) ? hbuf1 : hbuf0;
        float*       hout = (s & 1) ? hbuf0 : hbuf1;

        // issue gx loads first (DRAM latency hidden under staging + dot)
        const size_t gbase = ((size_t)b * T + t) * H3;
        const float xz = gx[gbase + j];
        const float xr = gx[gbase + H + j];
        const float xn = gx[gbase + 2 * H + j];

        // stage h (B x H) into smem; bypass L1 (written by other SMs)
        for (int idx = tid * 4; idx < B * H; idx += blockDim.x * 4) {
            int bb = idx >> 9;
            int kk = idx & (H - 1);
            float4 v = __ldcg(reinterpret_cast<const float4*>(hin + idx));
            *reinterpret_cast<float4*>(&h_s[bb * HP + kk]) = v;
        }
        __syncthreads();

        float az = 0.f, ar = 0.f, an = 0.f;
        const float* hr4 = &h_s[b * HP];
        const float* wz  = &W_s[cg * WP];
        const float* wr  = &W_s[(JS + cg) * WP];
        const float* wn  = &W_s[(2 * JS + cg) * WP];
#pragma unroll 4
        for (int k = 0; k < H; k += 4) {
            float4 hv = *reinterpret_cast<const float4*>(hr4 + k);
            float4 z4 = *reinterpret_cast<const float4*>(wz + k);
            float4 r4 = *reinterpret_cast<const float4*>(wr + k);
            float4 n4 = *reinterpret_cast<const float4*>(wn + k);
            az = fmaf(hv.x, z4.x, az); az = fmaf(hv.y, z4.y, az);
            az = fmaf(hv.z, z4.z, az); az = fmaf(hv.w, z4.w, az);
            ar = fmaf(hv.x, r4.x, ar); ar = fmaf(hv.y, r4.y, ar);
            ar = fmaf(hv.z, r4.z, ar); ar = fmaf(hv.w, r4.w, ar);
            an = fmaf(hv.x, n4.x, an); an = fmaf(hv.y, n4.y, an);
            an = fmaf(hv.z, n4.z, an); an = fmaf(hv.w, n4.w, an);
        }

        const float hprev = h_s[b * HP + j];
        const float zg = 1.f / (1.f + expf(-(xz + az + brz)));
        const float rg = 1.f / (1.f + expf(-(xr + ar + brr)));
        const float hc = tanhf(xn + rg * (an + brn));
        const float hnew = zg * hprev + (1.f - zg) * hc;

        __stcg(hout + b * H + j, hnew);
        g_outcat[((size_t)b * T + t) * H2 + dir * H + j] = hnew;
        if (s == T - 1) g_hcat[b * H2 + dir * H + j] = hnew;

        // per-direction grid barrier
        __threadfence();
        __syncthreads();
        if (tid == 0) {
            atomicAdd((unsigned*)&g_bar[dir], 1u);
            const unsigned target = (unsigned)(NB * (s + 1));
            while (*bar < target) {}
        }
        __syncthreads();
        __threadfence();
    }
}

// ---------------- launch ----------------
extern "C" void kernel_launch(void* const* d_in, const int* in_sizes, int n_in,
                              void* d_out, int out_size) {
    (void)in_sizes; (void)n_in; (void)out_size;
    const int*   seqs = (const int*)d_in[0];
    const float* emb  = (const float*)d_in[2];
    const float* Wx_f = (const float*)d_in[3];
    const float* Wh_f = (const float*)d_in[4];
    const float* b_f  = (const float*)d_in[5];
    const float* Wx_b = (const float*)d_in[6];
    const float* Wh_b = (const float*)d_in[7];
    const float* b_b  = (const float*)d_in[8];
    const float* Wd   = (const float*)d_in[9];
    const float* bd   = (const float*)d_in[10];
    float* out = (float*)d_out;

    const int smem_gru = (B * HP + 3 * JS * WP) * (int)sizeof(float); // 115,584 B
    cudaFuncSetAttribute(gru_kernel, cudaFuncAttributeMaxDynamicSharedMemorySize, smem_gru);

    float *p_embx, *p_gx0, *p_gx1, *p_outcat, *p_hcat;
    cudaGetSymbolAddress((void**)&p_embx,   g_embx);
    cudaGetSymbolAddress((void**)&p_gx0,    g_gx0);
    cudaGetSymbolAddress((void**)&p_gx1,    g_gx1);
    cudaGetSymbolAddress((void**)&p_outcat, g_outcat);
    cudaGetSymbolAddress((void**)&p_hcat,   g_hcat);

    init_kernel<<<64, 256>>>();
    embed_kernel<<<BT, 128>>>(seqs, emb);

    // gx = embedded @ Wx + b_in
    gemm_bias_kernel<<<dim3(H3 / 128, BT / 128), 256>>>(p_embx, Wx_f, b_f, p_gx0, BT, H3, H);
    gemm_bias_kernel<<<dim3(H3 / 128, BT / 128), 256>>>(p_embx, Wx_b, b_b, p_gx1, BT, H3, H);

    // bidirectional recurrence
    gru_kernel<<<2 * NB, 256, smem_gru>>>(Wh_f, b_f + H3, Wh_b, b_b + H3);

    // outputs / hidden projection
    gemm_bias_kernel<<<dim3(H / 128, BT / 128), 256>>>(p_outcat, Wd, bd, out, BT, H, H2);
    gemm_bias_kernel<<<dim3(H / 128, 1), 256>>>(p_hcat, Wd, bd, out + (size_t)BT * H, B, H, H2);
}

// round 3
// speedup vs baseline: 1.3093x; 1.3093x over previous
#include <cuda_runtime.h>
#include <cstdint>

#define B   32
#define T   512
#define MIN 4
#define H   512
#define H2  1024
#define H3  1536
#define BT  (B*T)

#define NB  64   // blocks per direction (JS*NB == H)
#define JS  8    // hidden dims per block

typedef unsigned long long ull;

// ---------------- f32x2 packed helpers (SASS FFMA2 path) ----------------
__device__ __forceinline__ ull fma2(ull a, ull b, ull c) {
    ull d;
    asm("fma.rn.f32x2 %0, %1, %2, %3;" : "=l"(d) : "l"(a), "l"(b), "l"(c));
    return d;
}
__device__ __forceinline__ ull add2(ull a, ull b) {
    ull d;
    asm("add.rn.f32x2 %0, %1, %2;" : "=l"(d) : "l"(a), "l"(b));
    return d;
}
__device__ __forceinline__ ull packdup(float a) {
    ull r;
    asm("mov.b64 %0, {%1, %1};" : "=l"(r) : "f"(a));
    return r;
}
__device__ __forceinline__ float lo2(ull v) { return __uint_as_float((unsigned)v); }
__device__ __forceinline__ float hi2(ull v) { return __uint_as_float((unsigned)(v >> 32)); }

// ---------------- device scratch ----------------
__device__ float    g_embx[BT * H];
__device__ float    g_gx0[(size_t)BT * H3];
__device__ float    g_gx1[(size_t)BT * H3];
__device__ float    g_outcat[(size_t)BT * H2];
__device__ float    g_hcat[B * H2];
__device__ float    g_hbuf[2][2][B * H];
__device__ unsigned g_bar[2];

// ---------------- init ----------------
__global__ void init_kernel() {
    int tid = blockIdx.x * blockDim.x + threadIdx.x;
    if (tid < 2) g_bar[tid] = 0;
    for (int i = tid; i < B * H; i += gridDim.x * blockDim.x) {
        g_hbuf[0][0][i] = 0.f;
        g_hbuf[1][0][i] = 0.f;
    }
}

// ---------------- embedding gather + sum ----------------
__global__ void embed_kernel(const int* __restrict__ seqs,
                             const float* __restrict__ emb) {
    int bt = blockIdx.x;
    int i4 = threadIdx.x * 4;
    const int* s = seqs + bt * MIN;
    float4 acc = make_float4(0.f, 0.f, 0.f, 0.f);
#pragma unroll
    for (int m = 0; m < MIN; m++) {
        size_t row = (size_t)s[m] * H;
        float4 v = *reinterpret_cast<const float4*>(emb + row + i4);
        acc.x += v.x; acc.y += v.y; acc.z += v.z; acc.w += v.w;
    }
    *reinterpret_cast<float4*>(g_embx + (size_t)bt * H + i4) = acc;
}

// ---------------- fp32 GEMM via FFMA2: C = A@W + bias ----------------
// tile 128x128, BK=16, 256 threads, 8 rows x 4 col-pairs per thread.
__global__ void __launch_bounds__(256) gemm_bias_kernel(
        const float* __restrict__ A, const float* __restrict__ W,
        const float* __restrict__ bias, float* __restrict__ C,
        int Mr, int N, int K) {
    __shared__ float a_s[16][136];
    __shared__ float b_s[16][128];
    const int tid = threadIdx.x;
    const int m0  = blockIdx.y * 128;
    const int n0  = blockIdx.x * 128;
    const int tr  = tid >> 4;        // 8 m-rows
    const int tc  = tid & 15;        // 8 n-cols (4 pairs)

    ull acc2[8][4];
#pragma unroll
    for (int i = 0; i < 8; i++)
#pragma unroll
        for (int j = 0; j < 4; j++) acc2[i][j] = 0ull;

    for (int kt = 0; kt < K; kt += 16) {
#pragma unroll
        for (int l = 0; l < 2; l++) {
            int lin = tid + l * 256;
            int m  = lin >> 2;
            int kk = (lin & 3) * 4;
            float4 v = make_float4(0.f, 0.f, 0.f, 0.f);
            if (m0 + m < Mr)
                v = *reinterpret_cast<const float4*>(A + (size_t)(m0 + m) * K + kt + kk);
            a_s[kk + 0][m] = v.x; a_s[kk + 1][m] = v.y;
            a_s[kk + 2][m] = v.z; a_s[kk + 3][m] = v.w;
        }
#pragma unroll
        for (int l = 0; l < 2; l++) {
            int lin = tid + l * 256;
            int kk = lin >> 5;
            int n  = (lin & 31) * 4;
            *reinterpret_cast<float4*>(&b_s[kk][n]) =
                *reinterpret_cast<const float4*>(W + (size_t)(kt + kk) * N + n0 + n);
        }
        __syncthreads();
#pragma unroll
        for (int kk = 0; kk < 16; kk++) {
            float a[8];
            *reinterpret_cast<float4*>(&a[0]) = *reinterpret_cast<const float4*>(&a_s[kk][tr * 8]);
            *reinterpret_cast<float4*>(&a[4]) = *reinterpret_cast<const float4*>(&a_s[kk][tr * 8 + 4]);
            ulonglong2 b01 = *reinterpret_cast<const ulonglong2*>(&b_s[kk][tc * 8]);
            ulonglong2 b23 = *reinterpret_cast<const ulonglong2*>(&b_s[kk][tc * 8 + 4]);
            ull bb[4] = {b01.x, b01.y, b23.x, b23.y};
#pragma unroll
            for (int i = 0; i < 8; i++) {
                ull ad = packdup(a[i]);
#pragma unroll
                for (int j = 0; j < 4; j++)
                    acc2[i][j] = fma2(ad, bb[j], acc2[i][j]);
            }
        }
        __syncthreads();
    }
    ulonglong2 bv01 = *reinterpret_cast<const ulonglong2*>(bias + n0 + tc * 8);
    ulonglong2 bv23 = *reinterpret_cast<const ulonglong2*>(bias + n0 + tc * 8 + 4);
    ull bv[4] = {bv01.x, bv01.y, bv23.x, bv23.y};
#pragma unroll
    for (int i = 0; i < 8; i++) {
        int m = m0 + tr * 8 + i;
        if (m < Mr) {
            ulonglong2 s0, s1;
            s0.x = add2(acc2[i][0], bv[0]); s0.y = add2(acc2[i][1], bv[1]);
            s1.x = add2(acc2[i][2], bv[2]); s1.y = add2(acc2[i][3], bv[3]);
            *reinterpret_cast<ulonglong2*>(C + (size_t)m * N + n0 + tc * 8)     = s0;
            *reinterpret_cast<ulonglong2*>(C + (size_t)m * N + n0 + tc * 8 + 4) = s1;
        }
    }
}

// ---------------- persistent bidirectional GRU ----------------
// 128 blocks (64/dir), 256 threads. Thread = (jj 0..3, bq 0..7, kq 0..7):
// covers jt=2 j's x bt=4 batches, k-split 8 (k = kq*4 + 32*i, i=0..15).
// Partials reduced over kq (lane bits [0:3)) via shfl.bfly.
__global__ void __launch_bounds__(256) gru_kernel(
        const float* __restrict__ Wh_f, const float* __restrict__ brec_f,
        const float* __restrict__ Wh_b, const float* __restrict__ brec_b) {
    extern __shared__ float sm[];
    float* h_s = sm;              // [B][H]  (64KB)
    float* W_s = sm + B * H;      // [3*JS][H] rows: g*8 + local_j (48KB)

    const int dir = blockIdx.x >> 6;
    const int jb  = blockIdx.x & (NB - 1);
    const int j0  = jb * JS;
    const int tid = threadIdx.x;
    const int kq  = tid & 7;
    const int bq  = (tid >> 3) & 7;
    const int jj  = tid >> 6;                 // 0..3

    const float* Wh   = dir ? Wh_b   : Wh_f;
    const float* brec = dir ? brec_b : brec_f;
    const float* gx   = dir ? g_gx1  : g_gx0;

    // one-time weight stage, coalesced 32B segments per (k,gate)
    for (int idx = tid; idx < 3 * JS * H; idx += 256) {
        int k = idx / (3 * JS);
        int r = idx - k * (3 * JS);           // 0..23
        int g = r >> 3;
        int c = r & 7;
        W_s[(g * JS + c) * H + k] = Wh[(size_t)k * H3 + g * H + j0 + c];
    }
    float brg[3][2];
#pragma unroll
    for (int g = 0; g < 3; g++)
#pragma unroll
        for (int jj2 = 0; jj2 < 2; jj2++)
            brg[g][jj2] = brec[g * H + j0 + jj * 2 + jj2];
    __syncthreads();

    float* hbuf0 = g_hbuf[dir][0];
    float* hbuf1 = g_hbuf[dir][1];
    volatile unsigned* bar = &g_bar[dir];

    for (int s = 0; s < T; s++) {
        const int t = dir ? (T - 1 - s) : s;
        const float* hin  = (s & 1) ? hbuf1 : hbuf0;
        float*       hout = (s & 1) ? hbuf0 : hbuf1;

        // gx prefetch (finalize lanes only) — overlaps staging + dot
        float gxv[3][2][4];
        if (kq == 0) {
#pragma unroll
            for (int jj2 = 0; jj2 < 2; jj2++)
#pragma unroll
                for (int bi = 0; bi < 4; bi++) {
                    int b = bq * 4 + bi;
                    size_t gb = ((size_t)b * T + t) * H3 + j0 + jj * 2 + jj2;
                    gxv[0][jj2][bi] = __ldg(gx + gb);
                    gxv[1][jj2][bi] = __ldg(gx + gb + H);
                    gxv[2][jj2][bi] = __ldg(gx + gb + 2 * H);
                }
        }

        // stage h (L1 bypass — written by other SMs)
        for (int idx = tid * 4; idx < B * H; idx += 1024) {
            float4 v = __ldcg(reinterpret_cast<const float4*>(hin + idx));
            *reinterpret_cast<float4*>(h_s + idx) = v;
        }
        __syncthreads();

        // register-tiled packed dot: 48 f32x2 per 10 LDS.128 per iter
        ull acc[3][2][4];
#pragma unroll
        for (int g = 0; g < 3; g++)
#pragma unroll
            for (int a = 0; a < 2; a++)
#pragma unroll
                for (int c = 0; c < 4; c++) acc[g][a][c] = 0ull;

        const int kbase = kq * 4;
#pragma unroll 2
        for (int i = 0; i < 16; i++) {
            const int k = kbase + i * 32;
            ulonglong2 w[3][2];
#pragma unroll
            for (int g = 0; g < 3; g++)
#pragma unroll
                for (int jj2 = 0; jj2 < 2; jj2++)
                    w[g][jj2] = *reinterpret_cast<const ulonglong2*>(
                        &W_s[(g * JS + jj * 2 + jj2) * H + k]);
            ulonglong2 hv[4];
#pragma unroll
            for (int bi = 0; bi < 4; bi++)
                hv[bi] = *reinterpret_cast<const ulonglong2*>(&h_s[(bq * 4 + bi) * H + k]);
#pragma unroll
            for (int g = 0; g < 3; g++)
#pragma unroll
                for (int jj2 = 0; jj2 < 2; jj2++)
#pragma unroll
                    for (int bi = 0; bi < 4; bi++) {
                        acc[g][jj2][bi] = fma2(hv[bi].x, w[g][jj2].x, acc[g][jj2][bi]);
                        acc[g][jj2][bi] = fma2(hv[bi].y, w[g][jj2].y, acc[g][jj2][bi]);
                    }
        }

        // horizontal: pair-sum then reduce over kq lanes
        float red[3][2][4];
#pragma unroll
        for (int g = 0; g < 3; g++)
#pragma unroll
            for (int jj2 = 0; jj2 < 2; jj2++)
#pragma unroll
                for (int bi = 0; bi < 4; bi++) {
                    float x = lo2(acc[g][jj2][bi]) + hi2(acc[g][jj2][bi]);
                    x += __shfl_xor_sync(0xffffffffu, x, 1);
                    x += __shfl_xor_sync(0xffffffffu, x, 2);
                    x += __shfl_xor_sync(0xffffffffu, x, 4);
                    red[g][jj2][bi] = x;
                }

        if (kq == 0) {
#pragma unroll
            for (int jj2 = 0; jj2 < 2; jj2++)
#pragma unroll
                for (int bi = 0; bi < 4; bi++) {
                    const int j = j0 + jj * 2 + jj2;
                    const int b = bq * 4 + bi;
                    const float az = red[0][jj2][bi] + brg[0][jj2];
                    const float ar = red[1][jj2][bi] + brg[1][jj2];
                    const float an = red[2][jj2][bi] + brg[2][jj2];
                    const float hprev = h_s[b * H + j];
                    const float zg = 1.f / (1.f + expf(-(gxv[0][jj2][bi] + az)));
                    const float rg = 1.f / (1.f + expf(-(gxv[1][jj2][bi] + ar)));
                    const float hc = tanhf(gxv[2][jj2][bi] + rg * an);
                    const float hnew = zg * hprev + (1.f - zg) * hc;
                    __stcg(hout + b * H + j, hnew);
                    g_outcat[((size_t)b * T + t) * H2 + dir * H + j] = hnew;
                    if (s == T - 1) g_hcat[b * H2 + dir * H + j] = hnew;
                }
        }

        // per-direction grid barrier
        __threadfence();
        __syncthreads();
        if (tid == 0) {
            atomicAdd((unsigned*)&g_bar[dir], 1u);
            const unsigned target = (unsigned)(NB * (s + 1));
            while (*bar < target) {}
        }
        __syncthreads();
        __threadfence();
    }
}

// ---------------- launch ----------------
extern "C" void kernel_launch(void* const* d_in, const int* in_sizes, int n_in,
                              void* d_out, int out_size) {
    (void)in_sizes; (void)n_in; (void)out_size;
    const int*   seqs = (const int*)d_in[0];
    const float* emb  = (const float*)d_in[2];
    const float* Wx_f = (const float*)d_in[3];
    const float* Wh_f = (const float*)d_in[4];
    const float* b_f  = (const float*)d_in[5];
    const float* Wx_b = (const float*)d_in[6];
    const float* Wh_b = (const float*)d_in[7];
    const float* b_b  = (const float*)d_in[8];
    const float* Wd   = (const float*)d_in[9];
    const float* bd   = (const float*)d_in[10];
    float* out = (float*)d_out;

    const int smem_gru = (B * H + 3 * JS * H) * (int)sizeof(float); // 112 KB
    cudaFuncSetAttribute(gru_kernel, cudaFuncAttributeMaxDynamicSharedMemorySize, smem_gru);

    float *p_embx, *p_gx0, *p_gx1, *p_outcat, *p_hcat;
    cudaGetSymbolAddress((void**)&p_embx,   g_embx);
    cudaGetSymbolAddress((void**)&p_gx0,    g_gx0);
    cudaGetSymbolAddress((void**)&p_gx1,    g_gx1);
    cudaGetSymbolAddress((void**)&p_outcat, g_outcat);
    cudaGetSymbolAddress((void**)&p_hcat,   g_hcat);

    init_kernel<<<64, 256>>>();
    embed_kernel<<<BT, 128>>>(seqs, emb);

    gemm_bias_kernel<<<dim3(H3 / 128, BT / 128), 256>>>(p_embx, Wx_f, b_f, p_gx0, BT, H3, H);
    gemm_bias_kernel<<<dim3(H3 / 128, BT / 128), 256>>>(p_embx, Wx_b, b_b, p_gx1, BT, H3, H);

    gru_kernel<<<2 * NB, 256, smem_gru>>>(Wh_f, b_f + H3, Wh_b, b_b + H3);

    gemm_bias_kernel<<<dim3(H / 128, BT / 128), 256>>>(p_outcat, Wd, bd, out, BT, H, H2);
    gemm_bias_kernel<<<dim3(H / 128, 1), 256>>>(p_hcat, Wd, bd, out + (size_t)BT * H, B, H, H2);
}

// round 4
// speedup vs baseline: 1.3890x; 1.0609x over previous
#include <cuda_runtime.h>
#include <cstdint>

#define B   32
#define T   512
#define MIN 4
#define H   512
#define H2  1024
#define H3  1536
#define BT  (B*T)

#define NB  64   // blocks per direction (JS*NB == H)
#define JS  8    // hidden dims per block

typedef unsigned long long ull;

// ---------------- f32x2 packed helpers ----------------
__device__ __forceinline__ ull fma2(ull a, ull b, ull c) {
    ull d;
    asm("fma.rn.f32x2 %0, %1, %2, %3;" : "=l"(d) : "l"(a), "l"(b), "l"(c));
    return d;
}
__device__ __forceinline__ ull add2(ull a, ull b) {
    ull d;
    asm("add.rn.f32x2 %0, %1, %2;" : "=l"(d) : "l"(a), "l"(b));
    return d;
}
__device__ __forceinline__ ull packdup(float a) {
    ull r;
    asm("mov.b64 %0, {%1, %1};" : "=l"(r) : "f"(a));
    return r;
}
__device__ __forceinline__ float lo2(ull v) { return __uint_as_float((unsigned)v); }
__device__ __forceinline__ float hi2(ull v) { return __uint_as_float((unsigned)(v >> 32)); }

// ---------------- device scratch ----------------
__device__ float    g_embx[BT * H];
__device__ float    g_gx0[(size_t)BT * H3];
__device__ float    g_gx1[(size_t)BT * H3];
__device__ float    g_outcat[(size_t)BT * H2];
__device__ float    g_hcat[B * H2];
__device__ float    g_hbuf[2][2][B * H];
__device__ unsigned g_bar[2];

// ---------------- init ----------------
__global__ void init_kernel() {
    int tid = blockIdx.x * blockDim.x + threadIdx.x;
    if (tid < 2) g_bar[tid] = 0;
    for (int i = tid; i < B * H; i += gridDim.x * blockDim.x) {
        g_hbuf[0][0][i] = 0.f;
        g_hbuf[1][0][i] = 0.f;
    }
}

// ---------------- embedding gather + sum ----------------
__global__ void embed_kernel(const int* __restrict__ seqs,
                             const float* __restrict__ emb) {
    int bt = blockIdx.x;
    int i4 = threadIdx.x * 4;
    const int* s = seqs + bt * MIN;
    float4 acc = make_float4(0.f, 0.f, 0.f, 0.f);
#pragma unroll
    for (int m = 0; m < MIN; m++) {
        size_t row = (size_t)s[m] * H;
        float4 v = *reinterpret_cast<const float4*>(emb + row + i4);
        acc.x += v.x; acc.y += v.y; acc.z += v.z; acc.w += v.w;
    }
    *reinterpret_cast<float4*>(g_embx + (size_t)bt * H + i4) = acc;
}

// ---------------- fp32 GEMM, register double-buffered ----------------
// tile 128x128, BK=16, 256 threads, 8 rows x 4 col-pairs per thread.
__global__ void __launch_bounds__(256) gemm_bias_kernel(
        const float* __restrict__ A, const float* __restrict__ W,
        const float* __restrict__ bias, float* __restrict__ C,
        int Mr, int N, int K) {
    __shared__ float a_s[16][132];   // [k][m] transposed, pad 132 (2-way STS max)
    __shared__ float b_s[16][128];
    const int tid = threadIdx.x;
    const int m0  = blockIdx.y * 128;
    const int n0  = blockIdx.x * 128;
    const int tr  = tid >> 4;
    const int tc  = tid & 15;

    // per-thread tile-load coordinates
    const int mA0 = tid >> 2;            // 0..63
    const int mA1 = mA0 + 64;
    const int kA  = (tid & 3) * 4;
    const int kB0 = tid >> 5;            // 0..7
    const int kB1 = kB0 + 8;
    const int nB  = (tid & 31) * 4;

    const bool okA0 = (m0 + mA0) < Mr;
    const bool okA1 = (m0 + mA1) < Mr;
    const float* pA0 = A + (size_t)(m0 + mA0) * K + kA;
    const float* pA1 = A + (size_t)(m0 + mA1) * K + kA;
    const float* pB0 = W + (size_t)kB0 * N + n0 + nB;
    const float* pB1 = W + (size_t)kB1 * N + n0 + nB;

    float4 aR0, aR1, bR0, bR1;
    const float4 z4 = make_float4(0.f, 0.f, 0.f, 0.f);

    // prologue: tile 0
    aR0 = okA0 ? *reinterpret_cast<const float4*>(pA0) : z4;
    aR1 = okA1 ? *reinterpret_cast<const float4*>(pA1) : z4;
    bR0 = *reinterpret_cast<const float4*>(pB0);
    bR1 = *reinterpret_cast<const float4*>(pB1);
    a_s[kA + 0][mA0] = aR0.x; a_s[kA + 1][mA0] = aR0.y;
    a_s[kA + 2][mA0] = aR0.z; a_s[kA + 3][mA0] = aR0.w;
    a_s[kA + 0][mA1] = aR1.x; a_s[kA + 1][mA1] = aR1.y;
    a_s[kA + 2][mA1] = aR1.z; a_s[kA + 3][mA1] = aR1.w;
    *reinterpret_cast<float4*>(&b_s[kB0][nB]) = bR0;
    *reinterpret_cast<float4*>(&b_s[kB1][nB]) = bR1;
    __syncthreads();

    ull acc2[8][4];
#pragma unroll
    for (int i = 0; i < 8; i++)
#pragma unroll
        for (int j = 0; j < 4; j++) acc2[i][j] = 0ull;

    for (int kt = 0; kt < K; kt += 16) {
        const bool more = (kt + 16) < K;
        if (more) {
            aR0 = okA0 ? *reinterpret_cast<const float4*>(pA0 + kt + 16) : z4;
            aR1 = okA1 ? *reinterpret_cast<const float4*>(pA1 + kt + 16) : z4;
            bR0 = *reinterpret_cast<const float4*>(pB0 + (size_t)(kt + 16) * N);
            bR1 = *reinterpret_cast<const float4*>(pB1 + (size_t)(kt + 16) * N);
        }
#pragma unroll
        for (int kk = 0; kk < 16; kk++) {
            float a[8];
            *reinterpret_cast<float4*>(&a[0]) = *reinterpret_cast<const float4*>(&a_s[kk][tr * 8]);
            *reinterpret_cast<float4*>(&a[4]) = *reinterpret_cast<const float4*>(&a_s[kk][tr * 8 + 4]);
            ulonglong2 b01 = *reinterpret_cast<const ulonglong2*>(&b_s[kk][tc * 8]);
            ulonglong2 b23 = *reinterpret_cast<const ulonglong2*>(&b_s[kk][tc * 8 + 4]);
            ull bb[4] = {b01.x, b01.y, b23.x, b23.y};
#pragma unroll
            for (int i = 0; i < 8; i++) {
                ull ad = packdup(a[i]);
#pragma unroll
                for (int j = 0; j < 4; j++)
                    acc2[i][j] = fma2(ad, bb[j], acc2[i][j]);
            }
        }
        __syncthreads();
        if (more) {
            a_s[kA + 0][mA0] = aR0.x; a_s[kA + 1][mA0] = aR0.y;
            a_s[kA + 2][mA0] = aR0.z; a_s[kA + 3][mA0] = aR0.w;
            a_s[kA + 0][mA1] = aR1.x; a_s[kA + 1][mA1] = aR1.y;
            a_s[kA + 2][mA1] = aR1.z; a_s[kA + 3][mA1] = aR1.w;
            *reinterpret_cast<float4*>(&b_s[kB0][nB]) = bR0;
            *reinterpret_cast<float4*>(&b_s[kB1][nB]) = bR1;
            __syncthreads();
        }
    }

    ulonglong2 bv01 = *reinterpret_cast<const ulonglong2*>(bias + n0 + tc * 8);
    ulonglong2 bv23 = *reinterpret_cast<const ulonglong2*>(bias + n0 + tc * 8 + 4);
    ull bv[4] = {bv01.x, bv01.y, bv23.x, bv23.y};
#pragma unroll
    for (int i = 0; i < 8; i++) {
        int m = m0 + tr * 8 + i;
        if (m < Mr) {
            ulonglong2 s0, s1;
            s0.x = add2(acc2[i][0], bv[0]); s0.y = add2(acc2[i][1], bv[1]);
            s1.x = add2(acc2[i][2], bv[2]); s1.y = add2(acc2[i][3], bv[3]);
            *reinterpret_cast<ulonglong2*>(C + (size_t)m * N + n0 + tc * 8)     = s0;
            *reinterpret_cast<ulonglong2*>(C + (size_t)m * N + n0 + tc * 8 + 4) = s1;
        }
    }
}

// ---------------- persistent bidirectional GRU ----------------
// 128 blocks (64/dir), 256 threads. Thread = (kq 0..7, bq 0..7, jj 0..3):
// jt=2 j's x bt=4 batches x k-split 8. kq reduced via shfl.bfly (lane bits 0..2).
// h staged in two 32KB k-chunks; chunk1's LDG overlaps chunk0's dot.
__global__ void __launch_bounds__(256, 1) gru_kernel(
        const float* __restrict__ Wh_f, const float* __restrict__ brec_f,
        const float* __restrict__ Wh_b, const float* __restrict__ brec_b) {
    extern __shared__ float sm[];
    float* h_s = sm;              // [B][H]  (64KB)
    float* W_s = sm + B * H;      // [3*JS][H] (48KB)

    const int dir = blockIdx.x >> 6;
    const int jb  = blockIdx.x & (NB - 1);
    const int j0  = jb * JS;
    const int tid = threadIdx.x;
    const int kq  = tid & 7;
    const int bq  = (tid >> 3) & 7;
    const int jj  = tid >> 6;

    const float* Wh   = dir ? Wh_b   : Wh_f;
    const float* brec = dir ? brec_b : brec_f;
    const float* gx   = dir ? g_gx1  : g_gx0;

    for (int idx = tid; idx < 3 * JS * H; idx += 256) {
        int k = idx / (3 * JS);
        int r = idx - k * (3 * JS);
        int g = r >> 3;
        int c = r & 7;
        W_s[(g * JS + c) * H + k] = Wh[(size_t)k * H3 + g * H + j0 + c];
    }
    float brg[3][2];
#pragma unroll
    for (int g = 0; g < 3; g++)
#pragma unroll
        for (int jj2 = 0; jj2 < 2; jj2++)
            brg[g][jj2] = brec[g * H + j0 + jj * 2 + jj2];
    __syncthreads();

    float* hbuf0 = g_hbuf[dir][0];
    float* hbuf1 = g_hbuf[dir][1];
    volatile unsigned* bar = &g_bar[dir];

    // staging coords: per pass p, idx = tid*4 + p*1024 within a 8192-float chunk
    int sbb[8], skk[8];
#pragma unroll
    for (int p = 0; p < 8; p++) {
        int idx = tid * 4 + p * 1024;
        sbb[p] = idx >> 8;          // batch (256 floats per b within chunk)
        skk[p] = idx & 255;         // k offset within chunk
    }

    for (int s = 0; s < T; s++) {
        const int t = dir ? (T - 1 - s) : s;
        const float* hin  = (s & 1) ? hbuf1 : hbuf0;
        float*       hout = (s & 1) ? hbuf0 : hbuf1;

        // gx prefetch (finalize lanes only)
        float gxv[3][2][4];
        if (kq == 0) {
#pragma unroll
            for (int jj2 = 0; jj2 < 2; jj2++)
#pragma unroll
                for (int bi = 0; bi < 4; bi++) {
                    int b = bq * 4 + bi;
                    size_t gb = ((size_t)b * T + t) * H3 + j0 + jj * 2 + jj2;
                    gxv[0][jj2][bi] = __ldg(gx + gb);
                    gxv[1][jj2][bi] = __ldg(gx + gb + H);
                    gxv[2][jj2][bi] = __ldg(gx + gb + 2 * H);
                }
        }

        // chunk0 (k in [0,256)): load -> smem; then issue chunk1 loads
        float4 r[8];
#pragma unroll
        for (int p = 0; p < 8; p++)
            r[p] = __ldcg(reinterpret_cast<const float4*>(hin + sbb[p] * H + skk[p]));
#pragma unroll
        for (int p = 0; p < 8; p++)
            *reinterpret_cast<float4*>(&h_s[sbb[p] * H + skk[p]]) = r[p];
#pragma unroll
        for (int p = 0; p < 8; p++)
            r[p] = __ldcg(reinterpret_cast<const float4*>(hin + sbb[p] * H + 256 + skk[p]));
        __syncthreads();

        ull acc[3][2][4];
#pragma unroll
        for (int g = 0; g < 3; g++)
#pragma unroll
            for (int a = 0; a < 2; a++)
#pragma unroll
                for (int c = 0; c < 4; c++) acc[g][a][c] = 0ull;

        const int kbase = kq * 4;
        // dot over chunk0 while chunk1 LDGs are in flight
#pragma unroll 2
        for (int i = 0; i < 8; i++) {
            const int k = kbase + i * 32;
            ulonglong2 w[3][2];
#pragma unroll
            for (int g = 0; g < 3; g++)
#pragma unroll
                for (int jj2 = 0; jj2 < 2; jj2++)
                    w[g][jj2] = *reinterpret_cast<const ulonglong2*>(
                        &W_s[(g * JS + jj * 2 + jj2) * H + k]);
            ulonglong2 hv[4];
#pragma unroll
            for (int bi = 0; bi < 4; bi++)
                hv[bi] = *reinterpret_cast<const ulonglong2*>(&h_s[(bq * 4 + bi) * H + k]);
#pragma unroll
            for (int g = 0; g < 3; g++)
#pragma unroll
                for (int jj2 = 0; jj2 < 2; jj2++)
#pragma unroll
                    for (int bi = 0; bi < 4; bi++) {
                        acc[g][jj2][bi] = fma2(hv[bi].x, w[g][jj2].x, acc[g][jj2][bi]);
                        acc[g][jj2][bi] = fma2(hv[bi].y, w[g][jj2].y, acc[g][jj2][bi]);
                    }
        }
        // commit chunk1 to smem, then dot it
#pragma unroll
        for (int p = 0; p < 8; p++)
            *reinterpret_cast<float4*>(&h_s[sbb[p] * H + 256 + skk[p]]) = r[p];
        __syncthreads();
#pragma unroll 2
        for (int i = 8; i < 16; i++) {
            const int k = kbase + i * 32;
            ulonglong2 w[3][2];
#pragma unroll
            for (int g = 0; g < 3; g++)
#pragma unroll
                for (int jj2 = 0; jj2 < 2; jj2++)
                    w[g][jj2] = *reinterpret_cast<const ulonglong2*>(
                        &W_s[(g * JS + jj * 2 + jj2) * H + k]);
            ulonglong2 hv[4];
#pragma unroll
            for (int bi = 0; bi < 4; bi++)
                hv[bi] = *reinterpret_cast<const ulonglong2*>(&h_s[(bq * 4 + bi) * H + k]);
#pragma unroll
            for (int g = 0; g < 3; g++)
#pragma unroll
                for (int jj2 = 0; jj2 < 2; jj2++)
#pragma unroll
                    for (int bi = 0; bi < 4; bi++) {
                        acc[g][jj2][bi] = fma2(hv[bi].x, w[g][jj2].x, acc[g][jj2][bi]);
                        acc[g][jj2][bi] = fma2(hv[bi].y, w[g][jj2].y, acc[g][jj2][bi]);
                    }
        }

        // pair-sum + reduce over kq lanes
        float red[3][2][4];
#pragma unroll
        for (int g = 0; g < 3; g++)
#pragma unroll
            for (int jj2 = 0; jj2 < 2; jj2++)
#pragma unroll
                for (int bi = 0; bi < 4; bi++) {
                    float x = lo2(acc[g][jj2][bi]) + hi2(acc[g][jj2][bi]);
                    x += __shfl_xor_sync(0xffffffffu, x, 1);
                    x += __shfl_xor_sync(0xffffffffu, x, 2);
                    x += __shfl_xor_sync(0xffffffffu, x, 4);
                    red[g][jj2][bi] = x;
                }

        if (kq == 0) {
#pragma unroll
            for (int jj2 = 0; jj2 < 2; jj2++)
#pragma unroll
                for (int bi = 0; bi < 4; bi++) {
                    const int j = j0 + jj * 2 + jj2;
                    const int b = bq * 4 + bi;
                    const float az = red[0][jj2][bi] + brg[0][jj2];
                    const float ar = red[1][jj2][bi] + brg[1][jj2];
                    const float an = red[2][jj2][bi] + brg[2][jj2];
                    const float hprev = h_s[b * H + j];
                    const float zg = 1.f / (1.f + expf(-(gxv[0][jj2][bi] + az)));
                    const float rg = 1.f / (1.f + expf(-(gxv[1][jj2][bi] + ar)));
                    const float hc = tanhf(gxv[2][jj2][bi] + rg * an);
                    const float hnew = zg * hprev + (1.f - zg) * hc;
                    __stcg(hout + b * H + j, hnew);
                    g_outcat[((size_t)b * T + t) * H2 + dir * H + j] = hnew;
                    if (s == T - 1) g_hcat[b * H2 + dir * H + j] = hnew;
                }
        }

        // per-direction grid barrier: fences on arriving thread only
        __syncthreads();
        if (tid == 0) {
            __threadfence();                       // release block's writes (gpu scope)
            atomicAdd((unsigned*)&g_bar[dir], 1u);
            const unsigned target = (unsigned)(NB * (s + 1));
            while (*bar < target) {}
            __threadfence();                       // acquire
        }
        __syncthreads();
    }
}

// ---------------- launch ----------------
extern "C" void kernel_launch(void* const* d_in, const int* in_sizes, int n_in,
                              void* d_out, int out_size) {
    (void)in_sizes; (void)n_in; (void)out_size;
    const int*   seqs = (const int*)d_in[0];
    const float* emb  = (const float*)d_in[2];
    const float* Wx_f = (const float*)d_in[3];
    const float* Wh_f = (const float*)d_in[4];
    const float* b_f  = (const float*)d_in[5];
    const float* Wx_b = (const float*)d_in[6];
    const float* Wh_b = (const float*)d_in[7];
    const float* b_b  = (const float*)d_in[8];
    const float* Wd   = (const float*)d_in[9];
    const float* bd   = (const float*)d_in[10];
    float* out = (float*)d_out;

    const int smem_gru = (B * H + 3 * JS * H) * (int)sizeof(float); // 112 KB
    cudaFuncSetAttribute(gru_kernel, cudaFuncAttributeMaxDynamicSharedMemorySize, smem_gru);

    float *p_embx, *p_gx0, *p_gx1, *p_outcat, *p_hcat;
    cudaGetSymbolAddress((void**)&p_embx,   g_embx);
    cudaGetSymbolAddress((void**)&p_gx0,    g_gx0);
    cudaGetSymbolAddress((void**)&p_gx1,    g_gx1);
    cudaGetSymbolAddress((void**)&p_outcat, g_outcat);
    cudaGetSymbolAddress((void**)&p_hcat,   g_hcat);

    init_kernel<<<64, 256>>>();
    embed_kernel<<<BT, 128>>>(seqs, emb);

    gemm_bias_kernel<<<dim3(H3 / 128, BT / 128), 256>>>(p_embx, Wx_f, b_f, p_gx0, BT, H3, H);
    gemm_bias_kernel<<<dim3(H3 / 128, BT / 128), 256>>>(p_embx, Wx_b, b_b, p_gx1, BT, H3, H);

    gru_kernel<<<2 * NB, 256, smem_gru>>>(Wh_f, b_f + H3, Wh_b, b_b + H3);

    gemm_bias_kernel<<<dim3(H / 128, BT / 128), 256>>>(p_outcat, Wd, bd, out, BT, H, H2);
    gemm_bias_kernel<<<dim3(H / 128, 1), 256>>>(p_hcat, Wd, bd, out + (size_t)BT * H, B, H, H2);
}

// round 5
// speedup vs baseline: 1.5145x; 1.0904x over previous
#include <cuda_runtime.h>
#include <cstdint>

#define B   32
#define T   512
#define MIN 4
#define H   512
#define H2  1024
#define H3  1536
#define BT  (B*T)

#define NB  64
#define JS  8

typedef unsigned long long ull;

// ---------------- packed f32x2 helpers ----------------
__device__ __forceinline__ ull fma2(ull a, ull b, ull c) {
    ull d;
    asm("fma.rn.f32x2 %0, %1, %2, %3;" : "=l"(d) : "l"(a), "l"(b), "l"(c));
    return d;
}
__device__ __forceinline__ ull add2(ull a, ull b) {
    ull d;
    asm("add.rn.f32x2 %0, %1, %2;" : "=l"(d) : "l"(a), "l"(b));
    return d;
}
__device__ __forceinline__ ull packdup(float a) {
    ull r;
    asm("mov.b64 %0, {%1, %1};" : "=l"(r) : "f"(a));
    return r;
}
__device__ __forceinline__ float lo2(ull v) { return __uint_as_float((unsigned)v); }
__device__ __forceinline__ float hi2(ull v) { return __uint_as_float((unsigned)(v >> 32)); }

// ---------------- cp.async helpers ----------------
__device__ __forceinline__ void cp16(uint32_t smem, const void* gmem) {
    asm volatile("cp.async.cg.shared.global [%0], [%1], 16;" :: "r"(smem), "l"(gmem));
}
__device__ __forceinline__ void cp_commit() {
    asm volatile("cp.async.commit_group;");
}
template <int N>
__device__ __forceinline__ void cp_wait() {
    asm volatile("cp.async.wait_group %0;" :: "n"(N));
}

// ---------------- device scratch ----------------
__device__ float    g_embx[BT * H];
__device__ float    g_gx0[(size_t)BT * H3];
__device__ float    g_gx1[(size_t)BT * H3];
__device__ float    g_outcat[(size_t)BT * H2];
__device__ float    g_hcat[B * H2];
__device__ float    g_hbuf[2][2][B * H];
__device__ unsigned g_bar[2];

// ---------------- init ----------------
__global__ void init_kernel() {
    int tid = blockIdx.x * blockDim.x + threadIdx.x;
    if (tid < 2) g_bar[tid] = 0;
    for (int i = tid; i < B * H; i += gridDim.x * blockDim.x) {
        g_hbuf[0][0][i] = 0.f;
        g_hbuf[1][0][i] = 0.f;
    }
}

// ---------------- embedding gather + sum ----------------
__global__ void embed_kernel(const int* __restrict__ seqs,
                             const float* __restrict__ emb) {
    int bt = blockIdx.x;
    int i4 = threadIdx.x * 4;
    const int* s = seqs + bt * MIN;
    float4 acc = make_float4(0.f, 0.f, 0.f, 0.f);
#pragma unroll
    for (int m = 0; m < MIN; m++) {
        size_t row = (size_t)s[m] * H;
        float4 v = *reinterpret_cast<const float4*>(emb + row + i4);
        acc.x += v.x; acc.y += v.y; acc.z += v.z; acc.w += v.w;
    }
    *reinterpret_cast<float4*>(g_embx + (size_t)bt * H + i4) = acc;
}

// ---------------- fp32 GEMM: smem ping-pong + cp.async(B) ----------------
// tile 128x128, BK=16, 256 threads, 8x8 micro-tile, 2 CTAs/SM.
__global__ void __launch_bounds__(256, 2) gemm_bias_kernel(
        const float* __restrict__ A, const float* __restrict__ W,
        const float* __restrict__ bias, float* __restrict__ C,
        int Mr, int N, int K) {
    __shared__ float a_s[2][16][132];
    __shared__ float b_s[2][16][128];
    const int tid = threadIdx.x;
    const int m0  = blockIdx.y * 128;
    const int n0  = blockIdx.x * 128;
    const int tr  = tid >> 4;
    const int tc  = tid & 15;

    const int mA0 = tid >> 2;
    const int mA1 = mA0 + 64;
    const int kA  = (tid & 3) * 4;
    const int kB0 = tid >> 5;            // 0..7
    const int kB1 = kB0 + 8;
    const int nB  = (tid & 31) * 4;

    const bool okA0 = (m0 + mA0) < Mr;
    const bool okA1 = (m0 + mA1) < Mr;
    const float* pA0 = A + (size_t)(m0 + mA0) * K + kA;
    const float* pA1 = A + (size_t)(m0 + mA1) * K + kA;
    const float* pB0 = W + (size_t)kB0 * N + n0 + nB;
    const float* pB1 = W + (size_t)kB1 * N + n0 + nB;

    uint32_t bs0 = (uint32_t)__cvta_generic_to_shared(&b_s[0][kB0][nB]);
    uint32_t bs1 = (uint32_t)__cvta_generic_to_shared(&b_s[0][kB1][nB]);
    const uint32_t bstride = (uint32_t)(16 * 128 * sizeof(float)); // buffer stride

    const float4 z4 = make_float4(0.f, 0.f, 0.f, 0.f);
    float4 aR0, aR1;

    // prologue: buffer 0
    aR0 = okA0 ? *reinterpret_cast<const float4*>(pA0) : z4;
    aR1 = okA1 ? *reinterpret_cast<const float4*>(pA1) : z4;
    cp16(bs0, pB0);
    cp16(bs1, pB1);
    cp_commit();
    a_s[0][kA + 0][mA0] = aR0.x; a_s[0][kA + 1][mA0] = aR0.y;
    a_s[0][kA + 2][mA0] = aR0.z; a_s[0][kA + 3][mA0] = aR0.w;
    a_s[0][kA + 0][mA1] = aR1.x; a_s[0][kA + 1][mA1] = aR1.y;
    a_s[0][kA + 2][mA1] = aR1.z; a_s[0][kA + 3][mA1] = aR1.w;
    cp_wait<0>();
    __syncthreads();

    ull acc2[8][4];
#pragma unroll
    for (int i = 0; i < 8; i++)
#pragma unroll
        for (int j = 0; j < 4; j++) acc2[i][j] = 0ull;

    int p = 0;
    for (int kt = 0; kt < K; kt += 16) {
        const bool more = (kt + 16) < K;
        if (more) {
            // prefetch next tile into buffer 1-p
            aR0 = okA0 ? *reinterpret_cast<const float4*>(pA0 + kt + 16) : z4;
            aR1 = okA1 ? *reinterpret_cast<const float4*>(pA1 + kt + 16) : z4;
            cp16(bs0 + (1 - p) * bstride, pB0 + (size_t)(kt + 16) * N);
            cp16(bs1 + (1 - p) * bstride, pB1 + (size_t)(kt + 16) * N);
            cp_commit();
        }
#pragma unroll
        for (int kk = 0; kk < 16; kk++) {
            float a[8];
            *reinterpret_cast<float4*>(&a[0]) = *reinterpret_cast<const float4*>(&a_s[p][kk][tr * 8]);
            *reinterpret_cast<float4*>(&a[4]) = *reinterpret_cast<const float4*>(&a_s[p][kk][tr * 8 + 4]);
            ulonglong2 b01 = *reinterpret_cast<const ulonglong2*>(&b_s[p][kk][tc * 8]);
            ulonglong2 b23 = *reinterpret_cast<const ulonglong2*>(&b_s[p][kk][tc * 8 + 4]);
            ull bb[4] = {b01.x, b01.y, b23.x, b23.y};
#pragma unroll
            for (int i = 0; i < 8; i++) {
                ull ad = packdup(a[i]);
#pragma unroll
                for (int j = 0; j < 4; j++)
                    acc2[i][j] = fma2(ad, bb[j], acc2[i][j]);
            }
        }
        if (more) {
            const int q = 1 - p;
            a_s[q][kA + 0][mA0] = aR0.x; a_s[q][kA + 1][mA0] = aR0.y;
            a_s[q][kA + 2][mA0] = aR0.z; a_s[q][kA + 3][mA0] = aR0.w;
            a_s[q][kA + 0][mA1] = aR1.x; a_s[q][kA + 1][mA1] = aR1.y;
            a_s[q][kA + 2][mA1] = aR1.z; a_s[q][kA + 3][mA1] = aR1.w;
            cp_wait<0>();
            __syncthreads();
            p = q;
        }
    }

    ulonglong2 bv01 = *reinterpret_cast<const ulonglong2*>(bias + n0 + tc * 8);
    ulonglong2 bv23 = *reinterpret_cast<const ulonglong2*>(bias + n0 + tc * 8 + 4);
    ull bv[4] = {bv01.x, bv01.y, bv23.x, bv23.y};
#pragma unroll
    for (int i = 0; i < 8; i++) {
        int m = m0 + tr * 8 + i;
        if (m < Mr) {
            ulonglong2 s0, s1;
            s0.x = add2(acc2[i][0], bv[0]); s0.y = add2(acc2[i][1], bv[1]);
            s1.x = add2(acc2[i][2], bv[2]); s1.y = add2(acc2[i][3], bv[3]);
            *reinterpret_cast<ulonglong2*>(C + (size_t)m * N + n0 + tc * 8)     = s0;
            *reinterpret_cast<ulonglong2*>(C + (size_t)m * N + n0 + tc * 8 + 4) = s1;
        }
    }
}

// ---------------- persistent bidirectional GRU ----------------
// 128 blocks, 256 threads. Thread=(kq,bq,jj): jt=2 j x bt=4 b x ksplit 8.
// h staged via cp.async.cg in two 32KB chunks; chunk1 lands during chunk0 dot.
__global__ void __launch_bounds__(256, 1) gru_kernel(
        const float* __restrict__ Wh_f, const float* __restrict__ brec_f,
        const float* __restrict__ Wh_b, const float* __restrict__ brec_b) {
    extern __shared__ float sm[];
    float* h_s = sm;              // [B][H]  64KB
    float* W_s = sm + B * H;      // [3*JS][H] 48KB

    const int dir = blockIdx.x >> 6;
    const int jb  = blockIdx.x & (NB - 1);
    const int j0  = jb * JS;
    const int tid = threadIdx.x;
    const int kq  = tid & 7;
    const int bq  = (tid >> 3) & 7;
    const int jj  = tid >> 6;

    const float* Wh   = dir ? Wh_b   : Wh_f;
    const float* brec = dir ? brec_b : brec_f;
    const float* gx   = dir ? g_gx1  : g_gx0;

    for (int idx = tid; idx < 3 * JS * H; idx += 256) {
        int k = idx / (3 * JS);
        int r = idx - k * (3 * JS);
        int g = r >> 3;
        int c = r & 7;
        W_s[(g * JS + c) * H + k] = Wh[(size_t)k * H3 + g * H + j0 + c];
    }
    float brg[3][2];
#pragma unroll
    for (int g = 0; g < 3; g++)
#pragma unroll
        for (int jj2 = 0; jj2 < 2; jj2++)
            brg[g][jj2] = brec[g * H + j0 + jj * 2 + jj2];
    __syncthreads();

    float* hbuf0 = g_hbuf[dir][0];
    float* hbuf1 = g_hbuf[dir][1];
    volatile unsigned* bar = &g_bar[dir];

    // staging coords (offsets into the B*H h array), chunk = k in [0,256)
    int soff[8];
#pragma unroll
    for (int pp = 0; pp < 8; pp++) {
        int idx = tid * 4 + pp * 1024;
        soff[pp] = (idx >> 8) * H + (idx & 255);
    }
    uint32_t hs_base = (uint32_t)__cvta_generic_to_shared(h_s);

    for (int s = 0; s < T; s++) {
        const int t = dir ? (T - 1 - s) : s;
        const float* hin  = (s & 1) ? hbuf1 : hbuf0;
        float*       hout = (s & 1) ? hbuf0 : hbuf1;

        // stage h: chunk0 group, chunk1 group (cp.async, no registers)
#pragma unroll
        for (int pp = 0; pp < 8; pp++)
            cp16(hs_base + soff[pp] * 4, hin + soff[pp]);
        cp_commit();
#pragma unroll
        for (int pp = 0; pp < 8; pp++)
            cp16(hs_base + (soff[pp] + 256) * 4, hin + soff[pp] + 256);
        cp_commit();

        // gx prefetch (finalize lanes only) — overlaps cp.async traffic
        float gxv[3][2][4];
        if (kq == 0) {
#pragma unroll
            for (int jj2 = 0; jj2 < 2; jj2++)
#pragma unroll
                for (int bi = 0; bi < 4; bi++) {
                    int b = bq * 4 + bi;
                    size_t gb = ((size_t)b * T + t) * H3 + j0 + jj * 2 + jj2;
                    gxv[0][jj2][bi] = __ldg(gx + gb);
                    gxv[1][jj2][bi] = __ldg(gx + gb + H);
                    gxv[2][jj2][bi] = __ldg(gx + gb + 2 * H);
                }
        }

        cp_wait<1>();          // chunk0 resident
        __syncthreads();

        ull acc[3][2][4];
#pragma unroll
        for (int g = 0; g < 3; g++)
#pragma unroll
            for (int a = 0; a < 2; a++)
#pragma unroll
                for (int c = 0; c < 4; c++) acc[g][a][c] = 0ull;

        const int kbase = kq * 4;
#pragma unroll 2
        for (int i = 0; i < 8; i++) {
            const int k = kbase + i * 32;
            ulonglong2 w[3][2];
#pragma unroll
            for (int g = 0; g < 3; g++)
#pragma unroll
                for (int jj2 = 0; jj2 < 2; jj2++)
                    w[g][jj2] = *reinterpret_cast<const ulonglong2*>(
                        &W_s[(g * JS + jj * 2 + jj2) * H + k]);
            ulonglong2 hv[4];
#pragma unroll
            for (int bi = 0; bi < 4; bi++)
                hv[bi] = *reinterpret_cast<const ulonglong2*>(&h_s[(bq * 4 + bi) * H + k]);
#pragma unroll
            for (int g = 0; g < 3; g++)
#pragma unroll
                for (int jj2 = 0; jj2 < 2; jj2++)
#pragma unroll
                    for (int bi = 0; bi < 4; bi++) {
                        acc[g][jj2][bi] = fma2(hv[bi].x, w[g][jj2].x, acc[g][jj2][bi]);
                        acc[g][jj2][bi] = fma2(hv[bi].y, w[g][jj2].y, acc[g][jj2][bi]);
                    }
        }
        cp_wait<0>();          // chunk1 resident
        __syncthreads();
#pragma unroll 2
        for (int i = 8; i < 16; i++) {
            const int k = kbase + i * 32;
            ulonglong2 w[3][2];
#pragma unroll
            for (int g = 0; g < 3; g++)
#pragma unroll
                for (int jj2 = 0; jj2 < 2; jj2++)
                    w[g][jj2] = *reinterpret_cast<const ulonglong2*>(
                        &W_s[(g * JS + jj * 2 + jj2) * H + k]);
            ulonglong2 hv[4];
#pragma unroll
            for (int bi = 0; bi < 4; bi++)
                hv[bi] = *reinterpret_cast<const ulonglong2*>(&h_s[(bq * 4 + bi) * H + k]);
#pragma unroll
            for (int g = 0; g < 3; g++)
#pragma unroll
                for (int jj2 = 0; jj2 < 2; jj2++)
#pragma unroll
                    for (int bi = 0; bi < 4; bi++) {
                        acc[g][jj2][bi] = fma2(hv[bi].x, w[g][jj2].x, acc[g][jj2][bi]);
                        acc[g][jj2][bi] = fma2(hv[bi].y, w[g][jj2].y, acc[g][jj2][bi]);
                    }
        }

        // pair-sum + reduce over kq lanes
        float red[3][2][4];
#pragma unroll
        for (int g = 0; g < 3; g++)
#pragma unroll
            for (int jj2 = 0; jj2 < 2; jj2++)
#pragma unroll
                for (int bi = 0; bi < 4; bi++) {
                    float x = lo2(acc[g][jj2][bi]) + hi2(acc[g][jj2][bi]);
                    x += __shfl_xor_sync(0xffffffffu, x, 1);
                    x += __shfl_xor_sync(0xffffffffu, x, 2);
                    x += __shfl_xor_sync(0xffffffffu, x, 4);
                    red[g][jj2][bi] = x;
                }

        if (kq == 0) {
#pragma unroll
            for (int jj2 = 0; jj2 < 2; jj2++)
#pragma unroll
                for (int bi = 0; bi < 4; bi++) {
                    const int j = j0 + jj * 2 + jj2;
                    const int b = bq * 4 + bi;
                    const float az = red[0][jj2][bi] + brg[0][jj2];
                    const float ar = red[1][jj2][bi] + brg[1][jj2];
                    const float an = red[2][jj2][bi] + brg[2][jj2];
                    const float hprev = h_s[b * H + j];
                    const float zg = 1.f / (1.f + expf(-(gxv[0][jj2][bi] + az)));
                    const float rg = 1.f / (1.f + expf(-(gxv[1][jj2][bi] + ar)));
                    const float hc = tanhf(gxv[2][jj2][bi] + rg * an);
                    const float hnew = zg * hprev + (1.f - zg) * hc;
                    __stcg(hout + b * H + j, hnew);
                    g_outcat[((size_t)b * T + t) * H2 + dir * H + j] = hnew;
                    if (s == T - 1) g_hcat[b * H2 + dir * H + j] = hnew;
                }
        }

        // per-direction grid barrier, fences on arriving thread only
        __syncthreads();
        if (tid == 0) {
            __threadfence();
            atomicAdd((unsigned*)&g_bar[dir], 1u);
            const unsigned target = (unsigned)(NB * (s + 1));
            while (*bar < target) {}
            __threadfence();
        }
        __syncthreads();
    }
}

// ---------------- launch ----------------
extern "C" void kernel_launch(void* const* d_in, const int* in_sizes, int n_in,
                              void* d_out, int out_size) {
    (void)in_sizes; (void)n_in; (void)out_size;
    const int*   seqs = (const int*)d_in[0];
    const float* emb  = (const float*)d_in[2];
    const float* Wx_f = (const float*)d_in[3];
    const float* Wh_f = (const float*)d_in[4];
    const float* b_f  = (const float*)d_in[5];
    const float* Wx_b = (const float*)d_in[6];
    const float* Wh_b = (const float*)d_in[7];
    const float* b_b  = (const float*)d_in[8];
    const float* Wd   = (const float*)d_in[9];
    const float* bd   = (const float*)d_in[10];
    float* out = (float*)d_out;

    const int smem_gru = (B * H + 3 * JS * H) * (int)sizeof(float); // 112 KB
    cudaFuncSetAttribute(gru_kernel, cudaFuncAttributeMaxDynamicSharedMemorySize, smem_gru);

    float *p_embx, *p_gx0, *p_gx1, *p_outcat, *p_hcat;
    cudaGetSymbolAddress((void**)&p_embx,   g_embx);
    cudaGetSymbolAddress((void**)&p_gx0,    g_gx0);
    cudaGetSymbolAddress((void**)&p_gx1,    g_gx1);
    cudaGetSymbolAddress((void**)&p_outcat, g_outcat);
    cudaGetSymbolAddress((void**)&p_hcat,   g_hcat);

    init_kernel<<<64, 256>>>();
    embed_kernel<<<BT, 128>>>(seqs, emb);

    gemm_bias_kernel<<<dim3(H3 / 128, BT / 128), 256>>>(p_embx, Wx_f, b_f, p_gx0, BT, H3, H);
    gemm_bias_kernel<<<dim3(H3 / 128, BT / 128), 256>>>(p_embx, Wx_b, b_b, p_gx1, BT, H3, H);

    gru_kernel<<<2 * NB, 256, smem_gru>>>(Wh_f, b_f + H3, Wh_b, b_b + H3);

    gemm_bias_kernel<<<dim3(H / 128, BT / 128), 256>>>(p_outcat, Wd, bd, out, BT, H, H2);
    gemm_bias_kernel<<<dim3(H / 128, 1), 256>>>(p_hcat, Wd, bd, out + (size_t)BT * H, B, H, H2);
}

// round 7
// speedup vs baseline: 1.6262x; 1.0737x over previous
#include <cuda_runtime.h>
#include <cstdint>

#define B   32
#define T   512
#define MIN 4
#define H   512
#define H2  1024
#define H3  1536
#define BT  (B*T)

#define NB  64
#define JS  8

typedef unsigned long long ull;

// ---------------- packed f32x2 helpers ----------------
__device__ __forceinline__ ull fma2(ull a, ull b, ull c) {
    ull d;
    asm("fma.rn.f32x2 %0, %1, %2, %3;" : "=l"(d) : "l"(a), "l"(b), "l"(c));
    return d;
}
__device__ __forceinline__ ull add2(ull a, ull b) {
    ull d;
    asm("add.rn.f32x2 %0, %1, %2;" : "=l"(d) : "l"(a), "l"(b));
    return d;
}
__device__ __forceinline__ ull packdup(float a) {
    ull r;
    asm("mov.b64 %0, {%1, %1};" : "=l"(r) : "f"(a));
    return r;
}
__device__ __forceinline__ float lo2(ull v) { return __uint_as_float((unsigned)v); }
__device__ __forceinline__ float hi2(ull v) { return __uint_as_float((unsigned)(v >> 32)); }

// ---------------- cp.async helpers ----------------
__device__ __forceinline__ void cp16(uint32_t smem, const void* gmem) {
    asm volatile("cp.async.cg.shared.global [%0], [%1], 16;" :: "r"(smem), "l"(gmem));
}
__device__ __forceinline__ void cp_commit() {
    asm volatile("cp.async.commit_group;");
}
template <int N>
__device__ __forceinline__ void cp_wait() {
    asm volatile("cp.async.wait_group %0;" :: "n"(N));
}

// ---------------- device scratch ----------------
__device__ float    g_embx[BT * H];
__device__ float    g_gx0[(size_t)BT * H3];
__device__ float    g_gx1[(size_t)BT * H3];
__device__ float    g_outcat[(size_t)BT * H2];
__device__ float    g_hcat[B * H2];
__device__ float    g_hbuf[2][2][B * H];
__device__ unsigned g_bar[2];

// ---------------- init ----------------
__global__ void init_kernel() {
    int tid = blockIdx.x * blockDim.x + threadIdx.x;
    if (tid < 2) g_bar[tid] = 0;
    for (int i = tid; i < B * H; i += gridDim.x * blockDim.x) {
        g_hbuf[0][0][i] = 0.f;
        g_hbuf[1][0][i] = 0.f;
    }
}

// ---------------- embedding gather + sum ----------------
__global__ void embed_kernel(const int* __restrict__ seqs,
                             const float* __restrict__ emb) {
    int bt = blockIdx.x;
    int i4 = threadIdx.x * 4;
    const int* s = seqs + bt * MIN;
    float4 acc = make_float4(0.f, 0.f, 0.f, 0.f);
#pragma unroll
    for (int m = 0; m < MIN; m++) {
        size_t row = (size_t)s[m] * H;
        float4 v = *reinterpret_cast<const float4*>(emb + row + i4);
        acc.x += v.x; acc.y += v.y; acc.z += v.z; acc.w += v.w;
    }
    *reinterpret_cast<float4*>(g_embx + (size_t)bt * H + i4) = acc;
}

// ---------------- fp32 GEMM: smem ping-pong + cp.async(B) ----------------
__global__ void __launch_bounds__(256, 2) gemm_bias_kernel(
        const float* __restrict__ A, const float* __restrict__ W,
        const float* __restrict__ bias, float* __restrict__ C,
        int Mr, int N, int K) {
    __shared__ float a_s[2][16][132];
    __shared__ float b_s[2][16][128];
    const int tid = threadIdx.x;
    const int m0  = blockIdx.y * 128;
    const int n0  = blockIdx.x * 128;
    const int tr  = tid >> 4;
    const int tc  = tid & 15;

    const int mA0 = tid >> 2;
    const int mA1 = mA0 + 64;
    const int kA  = (tid & 3) * 4;
    const int kB0 = tid >> 5;
    const int kB1 = kB0 + 8;
    const int nB  = (tid & 31) * 4;

    const bool okA0 = (m0 + mA0) < Mr;
    const bool okA1 = (m0 + mA1) < Mr;
    const float* pA0 = A + (size_t)(m0 + mA0) * K + kA;
    const float* pA1 = A + (size_t)(m0 + mA1) * K + kA;
    const float* pB0 = W + (size_t)kB0 * N + n0 + nB;
    const float* pB1 = W + (size_t)kB1 * N + n0 + nB;

    uint32_t bs0 = (uint32_t)__cvta_generic_to_shared(&b_s[0][kB0][nB]);
    uint32_t bs1 = (uint32_t)__cvta_generic_to_shared(&b_s[0][kB1][nB]);
    const uint32_t bstride = (uint32_t)(16 * 128 * sizeof(float));

    const float4 z4 = make_float4(0.f, 0.f, 0.f, 0.f);
    float4 aR0, aR1;

    aR0 = okA0 ? *reinterpret_cast<const float4*>(pA0) : z4;
    aR1 = okA1 ? *reinterpret_cast<const float4*>(pA1) : z4;
    cp16(bs0, pB0);
    cp16(bs1, pB1);
    cp_commit();
    a_s[0][kA + 0][mA0] = aR0.x; a_s[0][kA + 1][mA0] = aR0.y;
    a_s[0][kA + 2][mA0] = aR0.z; a_s[0][kA + 3][mA0] = aR0.w;
    a_s[0][kA + 0][mA1] = aR1.x; a_s[0][kA + 1][mA1] = aR1.y;
    a_s[0][kA + 2][mA1] = aR1.z; a_s[0][kA + 3][mA1] = aR1.w;
    cp_wait<0>();
    __syncthreads();

    ull acc2[8][4];
#pragma unroll
    for (int i = 0; i < 8; i++)
#pragma unroll
        for (int j = 0; j < 4; j++) acc2[i][j] = 0ull;

    int p = 0;
    for (int kt = 0; kt < K; kt += 16) {
        const bool more = (kt + 16) < K;
        if (more) {
            aR0 = okA0 ? *reinterpret_cast<const float4*>(pA0 + kt + 16) : z4;
            aR1 = okA1 ? *reinterpret_cast<const float4*>(pA1 + kt + 16) : z4;
            cp16(bs0 + (1 - p) * bstride, pB0 + (size_t)(kt + 16) * N);
            cp16(bs1 + (1 - p) * bstride, pB1 + (size_t)(kt + 16) * N);
            cp_commit();
        }
#pragma unroll
        for (int kk = 0; kk < 16; kk++) {
            float a[8];
            *reinterpret_cast<float4*>(&a[0]) = *reinterpret_cast<const float4*>(&a_s[p][kk][tr * 8]);
            *reinterpret_cast<float4*>(&a[4]) = *reinterpret_cast<const float4*>(&a_s[p][kk][tr * 8 + 4]);
            ulonglong2 b01 = *reinterpret_cast<const ulonglong2*>(&b_s[p][kk][tc * 8]);
            ulonglong2 b23 = *reinterpret_cast<const ulonglong2*>(&b_s[p][kk][tc * 8 + 4]);
            ull bb[4] = {b01.x, b01.y, b23.x, b23.y};
#pragma unroll
            for (int i = 0; i < 8; i++) {
                ull ad = packdup(a[i]);
#pragma unroll
                for (int j = 0; j < 4; j++)
                    acc2[i][j] = fma2(ad, bb[j], acc2[i][j]);
            }
        }
        if (more) {
            const int q = 1 - p;
            a_s[q][kA + 0][mA0] = aR0.x; a_s[q][kA + 1][mA0] = aR0.y;
            a_s[q][kA + 2][mA0] = aR0.z; a_s[q][kA + 3][mA0] = aR0.w;
            a_s[q][kA + 0][mA1] = aR1.x; a_s[q][kA + 1][mA1] = aR1.y;
            a_s[q][kA + 2][mA1] = aR1.z; a_s[q][kA + 3][mA1] = aR1.w;
            cp_wait<0>();
            __syncthreads();
            p = q;
        }
    }

    ulonglong2 bv01 = *reinterpret_cast<const ulonglong2*>(bias + n0 + tc * 8);
    ulonglong2 bv23 = *reinterpret_cast<const ulonglong2*>(bias + n0 + tc * 8 + 4);
    ull bv[4] = {bv01.x, bv01.y, bv23.x, bv23.y};
#pragma unroll
    for (int i = 0; i < 8; i++) {
        int m = m0 + tr * 8 + i;
        if (m < Mr) {
            ulonglong2 s0, s1;
            s0.x = add2(acc2[i][0], bv[0]); s0.y = add2(acc2[i][1], bv[1]);
            s1.x = add2(acc2[i][2], bv[2]); s1.y = add2(acc2[i][3], bv[3]);
            *reinterpret_cast<ulonglong2*>(C + (size_t)m * N + n0 + tc * 8)     = s0;
            *reinterpret_cast<ulonglong2*>(C + (size_t)m * N + n0 + tc * 8 + 4) = s1;
        }
    }
}

// ---------------- persistent bidirectional GRU ----------------
// 128 blocks, 256 threads. Thread=(kq,bq,jj). Atomic barrier (R5-proven),
// arrival hoisted before outcat stores; 4-stage cp.async h staging.
__global__ void __launch_bounds__(256, 1) gru_kernel(
        const float* __restrict__ Wh_f, const float* __restrict__ brec_f,
        const float* __restrict__ Wh_b, const float* __restrict__ brec_b) {
    extern __shared__ float sm[];
    float* h_s = sm;              // [B][H] 64KB
    float* W_s = sm + B * H;      // [3*JS][H] 48KB

    const int dir = blockIdx.x >> 6;
    const int jb  = blockIdx.x & (NB - 1);
    const int j0  = jb * JS;
    const int tid = threadIdx.x;
    const int kq  = tid & 7;
    const int bq  = (tid >> 3) & 7;
    const int jj  = tid >> 6;

    const float* Wh   = dir ? Wh_b   : Wh_f;
    const float* brec = dir ? brec_b : brec_f;
    const float* gx   = dir ? g_gx1  : g_gx0;

    for (int idx = tid; idx < 3 * JS * H; idx += 256) {
        int k = idx / (3 * JS);
        int r = idx - k * (3 * JS);
        int g = r >> 3;
        int c = r & 7;
        W_s[(g * JS + c) * H + k] = Wh[(size_t)k * H3 + g * H + j0 + c];
    }
    float2 brg[3];
#pragma unroll
    for (int g = 0; g < 3; g++)
        brg[g] = *reinterpret_cast<const float2*>(brec + g * H + j0 + jj * 2);
    __syncthreads();

    float* hbuf0 = g_hbuf[dir][0];
    float* hbuf1 = g_hbuf[dir][1];
    volatile unsigned* bar = &g_bar[dir];

    // staging coords: 4 chunks x 4 passes; chunk c covers k in [c*128,(c+1)*128)
    int soff[4];
#pragma unroll
    for (int pp = 0; pp < 4; pp++) {
        int idx = tid * 4 + pp * 1024;          // over B*128 floats
        soff[pp] = (idx >> 7) * H + (idx & 127);
    }
    uint32_t hs_base = (uint32_t)__cvta_generic_to_shared(h_s);

    for (int s = 0; s < T; s++) {
        const int t = dir ? (T - 1 - s) : s;
        const float* hin  = (s & 1) ? hbuf1 : hbuf0;
        float*       hout = (s & 1) ? hbuf0 : hbuf1;

        // stage h in 4 cp.async groups (16KB each)
#pragma unroll
        for (int c = 0; c < 4; c++) {
#pragma unroll
            for (int pp = 0; pp < 4; pp++)
                cp16(hs_base + (soff[pp] + c * 128) * 4, hin + soff[pp] + c * 128);
            cp_commit();
        }

        // gx prefetch (float2, finalize lanes only)
        float2 gxv[3][4];
        if (kq == 0) {
#pragma unroll
            for (int bi = 0; bi < 4; bi++) {
                int b = bq * 4 + bi;
                size_t gb = ((size_t)b * T + t) * H3 + j0 + jj * 2;
                gxv[0][bi] = *reinterpret_cast<const float2*>(gx + gb);
                gxv[1][bi] = *reinterpret_cast<const float2*>(gx + gb + H);
                gxv[2][bi] = *reinterpret_cast<const float2*>(gx + gb + 2 * H);
            }
        }

        ull acc[3][2][4];
#pragma unroll
        for (int g = 0; g < 3; g++)
#pragma unroll
            for (int a = 0; a < 2; a++)
#pragma unroll
                for (int c = 0; c < 4; c++) acc[g][a][c] = 0ull;

        const int kbase = kq * 4;
#pragma unroll
        for (int qc = 0; qc < 4; qc++) {
            if (qc == 0) cp_wait<3>();
            else if (qc == 1) cp_wait<2>();
            else if (qc == 2) cp_wait<1>();
            else cp_wait<0>();
            __syncthreads();
#pragma unroll
            for (int i = qc * 4; i < qc * 4 + 4; i++) {
                const int k = kbase + i * 32;
                ulonglong2 w[3][2];
#pragma unroll
                for (int g = 0; g < 3; g++)
#pragma unroll
                    for (int jj2 = 0; jj2 < 2; jj2++)
                        w[g][jj2] = *reinterpret_cast<const ulonglong2*>(
                            &W_s[(g * JS + jj * 2 + jj2) * H + k]);
                ulonglong2 hv[4];
#pragma unroll
                for (int bi = 0; bi < 4; bi++)
                    hv[bi] = *reinterpret_cast<const ulonglong2*>(&h_s[(bq * 4 + bi) * H + k]);
#pragma unroll
                for (int g = 0; g < 3; g++)
#pragma unroll
                    for (int jj2 = 0; jj2 < 2; jj2++)
#pragma unroll
                        for (int bi = 0; bi < 4; bi++) {
                            acc[g][jj2][bi] = fma2(hv[bi].x, w[g][jj2].x, acc[g][jj2][bi]);
                            acc[g][jj2][bi] = fma2(hv[bi].y, w[g][jj2].y, acc[g][jj2][bi]);
                        }
            }
        }

        // pair-sum + reduce over kq lanes (bits 0..2)
        float red[3][2][4];
#pragma unroll
        for (int g = 0; g < 3; g++)
#pragma unroll
            for (int jj2 = 0; jj2 < 2; jj2++)
#pragma unroll
                for (int bi = 0; bi < 4; bi++) {
                    float x = lo2(acc[g][jj2][bi]) + hi2(acc[g][jj2][bi]);
                    x += __shfl_xor_sync(0xffffffffu, x, 1);
                    x += __shfl_xor_sync(0xffffffffu, x, 2);
                    x += __shfl_xor_sync(0xffffffffu, x, 4);
                    red[g][jj2][bi] = x;
                }

        // finalize + publish h (float2 per bi)
        float2 hnew2[4];
        if (kq == 0) {
#pragma unroll
            for (int bi = 0; bi < 4; bi++) {
                const int b = bq * 4 + bi;
                const float2 hp = *reinterpret_cast<const float2*>(&h_s[b * H + j0 + jj * 2]);
                float hn[2];
#pragma unroll
                for (int jj2 = 0; jj2 < 2; jj2++) {
                    const float az = red[0][jj2][bi] + ((jj2) ? brg[0].y : brg[0].x);
                    const float ar = red[1][jj2][bi] + ((jj2) ? brg[1].y : brg[1].x);
                    const float an = red[2][jj2][bi] + ((jj2) ? brg[2].y : brg[2].x);
                    const float xz = (jj2) ? gxv[0][bi].y : gxv[0][bi].x;
                    const float xr = (jj2) ? gxv[1][bi].y : gxv[1][bi].x;
                    const float xn = (jj2) ? gxv[2][bi].y : gxv[2][bi].x;
                    const float hprev = (jj2) ? hp.y : hp.x;
                    const float zg = 1.f / (1.f + expf(-(xz + az)));
                    const float rg = 1.f / (1.f + expf(-(xr + ar)));
                    const float hc = tanhf(xn + rg * an);
                    hn[jj2] = zg * hprev + (1.f - zg) * hc;
                }
                hnew2[bi] = make_float2(hn[0], hn[1]);
                asm volatile("st.global.cg.v2.f32 [%0], {%1, %2};"
                             :: "l"(hout + b * H + j0 + jj * 2), "f"(hn[0]), "f"(hn[1]));
            }
        }

        // arrive early: h published; outcat happens while others arrive
        __syncthreads();
        if (tid == 0) {
            __threadfence();
            atomicAdd((unsigned*)&g_bar[dir], 1u);
        }

        // outcat/hcat stores (not consumed by other blocks this step)
        if (kq == 0) {
#pragma unroll
            for (int bi = 0; bi < 4; bi++) {
                const int b = bq * 4 + bi;
                *reinterpret_cast<float2*>(&g_outcat[((size_t)b * T + t) * H2 + dir * H + j0 + jj * 2]) = hnew2[bi];
                if (s == T - 1)
                    *reinterpret_cast<float2*>(&g_hcat[b * H2 + dir * H + j0 + jj * 2]) = hnew2[bi];
            }
        }

        // wait: tid0-only spin on the counter (R5-proven)
        if (tid == 0) {
            const unsigned target = (unsigned)(NB * (s + 1));
            while (*bar < target) {}
            __threadfence();
        }
        __syncthreads();
    }
}

// ---------------- launch ----------------
extern "C" void kernel_launch(void* const* d_in, const int* in_sizes, int n_in,
                              void* d_out, int out_size) {
    (void)in_sizes; (void)n_in; (void)out_size;
    const int*   seqs = (const int*)d_in[0];
    const float* emb  = (const float*)d_in[2];
    const float* Wx_f = (const float*)d_in[3];
    const float* Wh_f = (const float*)d_in[4];
    const float* b_f  = (const float*)d_in[5];
    const float* Wx_b = (const float*)d_in[6];
    const float* Wh_b = (const float*)d_in[7];
    const float* b_b  = (const float*)d_in[8];
    const float* Wd   = (const float*)d_in[9];
    const float* bd   = (const float*)d_in[10];
    float* out = (float*)d_out;

    const int smem_gru = (B * H + 3 * JS * H) * (int)sizeof(float); // 112 KB
    cudaFuncSetAttribute(gru_kernel, cudaFuncAttributeMaxDynamicSharedMemorySize, smem_gru);

    float *p_embx, *p_gx0, *p_gx1, *p_outcat, *p_hcat;
    cudaGetSymbolAddress((void**)&p_embx,   g_embx);
    cudaGetSymbolAddress((void**)&p_gx0,    g_gx0);
    cudaGetSymbolAddress((void**)&p_gx1,    g_gx1);
    cudaGetSymbolAddress((void**)&p_outcat, g_outcat);
    cudaGetSymbolAddress((void**)&p_hcat,   g_hcat);

    init_kernel<<<64, 256>>>();
    embed_kernel<<<BT, 128>>>(seqs, emb);

    gemm_bias_kernel<<<dim3(H3 / 128, BT / 128), 256>>>(p_embx, Wx_f, b_f, p_gx0, BT, H3, H);
    gemm_bias_kernel<<<dim3(H3 / 128, BT / 128), 256>>>(p_embx, Wx_b, b_b, p_gx1, BT, H3, H);

    gru_kernel<<<2 * NB, 256, smem_gru>>>(Wh_f, b_f + H3, Wh_b, b_b + H3);

    gemm_bias_kernel<<<dim3(H / 128, BT / 128), 256>>>(p_outcat, Wd, bd, out, BT, H, H2);
    gemm_bias_kernel<<<dim3(H / 128, 1), 256>>>(p_hcat, Wd, bd, out + (size_t)BT * H, B, H, H2);
}